// round 8
// baseline (speedup 1.0000x reference)
#include <cuda_runtime.h>
#include <cuda_bf16.h>
#include <math.h>
#include <stdint.h>

// Problem constants
#define BATCH 8
#define HH 64
#define WW 64
#define DD 512
#define NHEAD 16
#define DK 32
#define WS 8
#define SHIFT 4
#define TOK (BATCH*HH*WW)      // 32768
#define LAYERS 4
#define SCALE 0.17677669529663687f  // 1/sqrt(32)

// -------------------- scratch (allocation-free: __device__ globals) ------------
// bf16 "pair" activations: [hi | lo] along K (row stride 2K)
__device__ __align__(128) unsigned short g_xn2 [ (size_t)TOK * 2 * DD ];       // 64 MB
__device__ __align__(128) unsigned short g_hb2 [ (size_t)TOK * 2 * DD ];       // 64 MB
__device__ __align__(128) unsigned short g_ao2 [ (size_t)TOK * 2 * DD ];       // 64 MB
__device__ __align__(128) unsigned short g_hid2[ (size_t)TOK * 2 * 4 * DD ];   // 256 MB
__device__ __align__(128) unsigned short g_w2  [ 25165824 ];                   // 48 MB [N][2K]=[Wh|Wl]
__device__ float g_qkv [ (size_t)TOK * 3 * DD ];                               // 201 MB
__device__ float g_bqkv[ LAYERS * 3 * DD ];

// ==================== helpers ==================================================
__device__ __forceinline__ uint32_t smem_u32(const void* p) {
    uint32_t a;
    asm("{ .reg .u64 t; cvta.to.shared.u64 t, %1; cvt.u32.u64 %0, t; }" : "=r"(a) : "l"(p));
    return a;
}
#define CP_ASYNC16(dst, src) \
    asm volatile("cp.async.cg.shared.global [%0], [%1], 16;" :: "r"(dst), "l"(src))
#define CP_COMMIT() asm volatile("cp.async.commit_group;" ::: "memory")
#define CP_WAIT1()  asm volatile("cp.async.wait_group 1;" ::: "memory")
#define CP_WAIT0()  asm volatile("cp.async.wait_group 0;" ::: "memory")

__device__ __forceinline__ void ldmx4(uint32_t& r0, uint32_t& r1, uint32_t& r2, uint32_t& r3,
                                      uint32_t addr) {
    asm volatile("ldmatrix.sync.aligned.m8n8.x4.shared.b16 {%0,%1,%2,%3}, [%4];"
                 : "=r"(r0), "=r"(r1), "=r"(r2), "=r"(r3) : "r"(addr));
}
__device__ __forceinline__ void mma16816(float* d, uint32_t a0, uint32_t a1, uint32_t a2,
                                         uint32_t a3, uint32_t b0, uint32_t b1) {
    asm volatile("mma.sync.aligned.m16n8k16.row.col.f32.bf16.bf16.f32 "
                 "{%0,%1,%2,%3},{%4,%5,%6,%7},{%8,%9},{%0,%1,%2,%3};"
                 : "+f"(d[0]), "+f"(d[1]), "+f"(d[2]), "+f"(d[3])
                 : "r"(a0), "r"(a1), "r"(a2), "r"(a3), "r"(b0), "r"(b1));
}

__device__ __forceinline__ void split_bf16(float v, unsigned short& hi, unsigned short& lo) {
    __nv_bfloat16 h = __float2bfloat16(v);
    hi = __bfloat16_as_ushort(h);
    lo = __bfloat16_as_ushort(__float2bfloat16(v - __bfloat162float(h)));
}
__device__ __forceinline__ float gelu_tanh(float x) {
    float x3 = x * x * x;
    return 0.5f * x * (1.0f + tanhf(0.7978845608028654f * (x + 0.044715f * x3)));
}

// ==================== weight convert: W[K,N] -> Wp[N, 2K] = [Wh|Wl] ============
// dst rows length 2K, layer stride zstride (elements)
__global__ void convw_kernel(const float* __restrict__ src, unsigned short* __restrict__ dst,
                             int K, int N, size_t zstride) {
    __shared__ float t[32][33];
    int n0 = blockIdx.x * 32, k0 = blockIdx.y * 32;
    src += (size_t)blockIdx.z * K * N;
    dst += (size_t)blockIdx.z * zstride;
    int tx = threadIdx.x, ty = threadIdx.y;
#pragma unroll
    for (int i = 0; i < 4; i++)
        t[ty + i * 8][tx] = src[(size_t)(k0 + ty + i * 8) * N + n0 + tx];
    __syncthreads();
#pragma unroll
    for (int i = 0; i < 4; i++) {
        int n = n0 + ty + i * 8;
        int k = k0 + tx;
        float v = t[tx][ty + i * 8];
        unsigned short hi, lo;
        split_bf16(v, hi, lo);
        size_t rb = (size_t)n * 2 * K;
        dst[rb + k] = hi;
        dst[rb + K + k] = lo;
    }
}

// ==================== bias concat for fused QKV ================================
__global__ void bcat_kernel(const float* __restrict__ bq, const float* __restrict__ bkv,
                            float* __restrict__ out) {
    int i = blockIdx.x * 256 + threadIdx.x;
    if (i >= LAYERS * 3 * DD) return;
    int l = i / (3 * DD), c = i % (3 * DD);
    out[i] = (c < DD) ? bq[l * DD + c] : bkv[l * 2 * DD + (c - DD)];
}

// ==================== LayerNorm -> bf16 pair ===================================
__global__ __launch_bounds__(128) void ln_kernel(const float* __restrict__ x,
                                                 const float* __restrict__ gamma,
                                                 const float* __restrict__ beta,
                                                 unsigned short* __restrict__ out) {
    int tok = blockIdx.x;
    int tid = threadIdx.x;
    const float* xr = x + (size_t)tok * DD;
    float v[4];
#pragma unroll
    for (int i = 0; i < 4; i++) v[i] = xr[tid + i * 128];

    __shared__ float s1[4], s2[4];
    int lane = tid & 31, warp = tid >> 5;

    float s = v[0] + v[1] + v[2] + v[3];
#pragma unroll
    for (int o = 16; o > 0; o >>= 1) s += __shfl_xor_sync(0xffffffffu, s, o);
    if (lane == 0) s1[warp] = s;
    __syncthreads();
    float mean = (s1[0] + s1[1] + s1[2] + s1[3]) * (1.0f / DD);

    float sq = 0.f;
#pragma unroll
    for (int i = 0; i < 4; i++) { float d = v[i] - mean; sq += d * d; }
#pragma unroll
    for (int o = 16; o > 0; o >>= 1) sq += __shfl_xor_sync(0xffffffffu, sq, o);
    if (lane == 0) s2[warp] = sq;
    __syncthreads();
    float var = (s2[0] + s2[1] + s2[2] + s2[3]) * (1.0f / DD);
    float rs = rsqrtf(var + 1e-5f);

    unsigned short* orow = out + (size_t)tok * 2 * DD;
#pragma unroll
    for (int i = 0; i < 4; i++) {
        int c = tid + i * 128;
        float o = (v[i] - mean) * rs * gamma[c] + beta[c];
        unsigned short hi, lo;
        split_bf16(o, hi, lo);
        orow[c] = hi;
        orow[DD + c] = lo;
    }
}

// ==================== bf16 mma GEMM (hi/lo packed chunks) ======================
// C[M,N] = epilogue(A2[M,2K] @ Wp[N,2K]^T) with 3-product schedule per chunk:
//   acc += Ah*Wh + Al*Wh + Ah*Wl
// chunk = 32 fp32 K; stage tile rows are 128B: [hi 64B | lo 64B]
// mode 0: fp32 out (+bias, +optional resid)   mode 1: gelu -> bf16 pair out
#define GSTAGES 3
#define GSTAGE_BYTES 32768     // A 16KB + B 16KB
#define GSB_OFF 16384
#define GEMM_SMEM (GSTAGES * GSTAGE_BYTES)

__global__ __launch_bounds__(256, 2) void gemm_mma(const unsigned short* __restrict__ A2,
                                                   const unsigned short* __restrict__ Wp,
                                                   const float* __restrict__ bias,
                                                   const float* __restrict__ resid,
                                                   void* __restrict__ Cout,
                                                   int N, int K, int mode) {
    extern __shared__ char smem[];
    uint32_t sb = smem_u32(smem);
    int tid = threadIdx.x, wid = tid >> 5, lane = tid & 31;
    int bm0 = blockIdx.y * 128, bn0 = blockIdx.x * 128;
    int wm = (wid & 3) * 32, wn = (wid >> 2) * 64;

    float acc[2][8][4];
#pragma unroll
    for (int t = 0; t < 2; t++)
#pragma unroll
        for (int n = 0; n < 8; n++)
#pragma unroll
            for (int r = 0; r < 4; r++) acc[t][n][r] = 0.f;

    const int nch = K >> 5;          // 32 fp32-K per chunk

    // loader: row = tid>>1, 4 x 16B slots with g = (tid&1)*4 + i
    // g<4 -> hi half (src offset c*32 + g*8), g>=4 -> lo half (src offset K + c*32 + (g-4)*8)
    int lr = tid >> 1;
    int khalf = tid & 1;
    const unsigned short* agp = A2 + (size_t)(bm0 + lr) * (2 * K) + (size_t)khalf * K;
    const unsigned short* bgp = Wp + (size_t)(bn0 + lr) * (2 * K) + (size_t)khalf * K;
    uint32_t sw[4];
#pragma unroll
    for (int i = 0; i < 4; i++)
        sw[i] = (uint32_t)lr * 128 + (uint32_t)(((khalf * 4 + i) ^ (lr & 7)) << 4);

    // ldmatrix per-warp bases
    int arow[2], arx[2];
#pragma unroll
    for (int t = 0; t < 2; t++) {
        int r = wm + t * 16 + (lane & 15);
        arow[t] = r * 128;
        arx[t] = r & 7;
    }
    int ach = lane >> 4;
    int brow[4], brx[4];
#pragma unroll
    for (int p = 0; p < 4; p++) {
        int n = wn + p * 16 + (lane & 7) + ((lane >> 4) << 3);
        brow[p] = n * 128;
        brx[p] = n & 7;
    }
    int bch = (lane >> 3) & 1;

    auto issue_stage = [&](int c, int stage) {
        uint32_t st = sb + (uint32_t)stage * GSTAGE_BYTES;
        const unsigned short* ag = agp + (size_t)c * 32;
        const unsigned short* bg = bgp + (size_t)c * 32;
#pragma unroll
        for (int i = 0; i < 4; i++) CP_ASYNC16(st + sw[i], ag + i * 8);
#pragma unroll
        for (int i = 0; i < 4; i++) CP_ASYNC16(st + GSB_OFF + sw[i], bg + i * 8);
        CP_COMMIT();
    };

    issue_stage(0, 0);
    issue_stage(1, 1);

    int buf = 0, nbuf = 2;
    for (int c = 0; c < nch; c++) {
        if (c == nch - 1) { CP_WAIT0(); } else { CP_WAIT1(); }
        __syncthreads();
        if (c + 2 < nch) issue_stage(c + 2, nbuf);

        uint32_t stA = sb + (uint32_t)buf * GSTAGE_BYTES;
        uint32_t stB = stA + GSB_OFF;
#pragma unroll
        for (int ks = 0; ks < 2; ks++) {
            uint32_t ah[2][4], al[2][4];
            int ghi = (ks << 1) + ach;
#pragma unroll
            for (int t = 0; t < 2; t++) {
                uint32_t adh = stA + arow[t] + (uint32_t)((ghi ^ arx[t]) << 4);
                ldmx4(ah[t][0], ah[t][1], ah[t][2], ah[t][3], adh);
                uint32_t adl = stA + arow[t] + (uint32_t)(((ghi + 4) ^ arx[t]) << 4);
                ldmx4(al[t][0], al[t][1], al[t][2], al[t][3], adl);
            }
            int gb = (ks << 1) + bch;
#pragma unroll
            for (int p = 0; p < 4; p++) {
                uint32_t bh0, bh1, bh2, bh3, bl0, bl1, bl2, bl3;
                uint32_t bdh = stB + brow[p] + (uint32_t)((gb ^ brx[p]) << 4);
                ldmx4(bh0, bh1, bh2, bh3, bdh);
                uint32_t bdl = stB + brow[p] + (uint32_t)(((gb + 4) ^ brx[p]) << 4);
                ldmx4(bl0, bl1, bl2, bl3, bdl);
                // Ah * Wh
                mma16816(acc[0][2 * p],     ah[0][0], ah[0][1], ah[0][2], ah[0][3], bh0, bh1);
                mma16816(acc[0][2 * p + 1], ah[0][0], ah[0][1], ah[0][2], ah[0][3], bh2, bh3);
                mma16816(acc[1][2 * p],     ah[1][0], ah[1][1], ah[1][2], ah[1][3], bh0, bh1);
                mma16816(acc[1][2 * p + 1], ah[1][0], ah[1][1], ah[1][2], ah[1][3], bh2, bh3);
                // Al * Wh
                mma16816(acc[0][2 * p],     al[0][0], al[0][1], al[0][2], al[0][3], bh0, bh1);
                mma16816(acc[0][2 * p + 1], al[0][0], al[0][1], al[0][2], al[0][3], bh2, bh3);
                mma16816(acc[1][2 * p],     al[1][0], al[1][1], al[1][2], al[1][3], bh0, bh1);
                mma16816(acc[1][2 * p + 1], al[1][0], al[1][1], al[1][2], al[1][3], bh2, bh3);
                // Ah * Wl
                mma16816(acc[0][2 * p],     ah[0][0], ah[0][1], ah[0][2], ah[0][3], bl0, bl1);
                mma16816(acc[0][2 * p + 1], ah[0][0], ah[0][1], ah[0][2], ah[0][3], bl2, bl3);
                mma16816(acc[1][2 * p],     ah[1][0], ah[1][1], ah[1][2], ah[1][3], bl0, bl1);
                mma16816(acc[1][2 * p + 1], ah[1][0], ah[1][1], ah[1][2], ah[1][3], bl2, bl3);
            }
        }
        buf = (buf + 1 == GSTAGES) ? 0 : buf + 1;
        nbuf = (nbuf + 1 == GSTAGES) ? 0 : nbuf + 1;
    }

    // epilogue
    int cbase = bn0 + wn;
#pragma unroll
    for (int t = 0; t < 2; t++) {
        int r0 = bm0 + wm + t * 16 + (lane >> 2);
#pragma unroll
        for (int half = 0; half < 2; half++) {
            int r = r0 + half * 8;
            if (mode == 0) {
                float* crow = (float*)Cout + (size_t)r * N + cbase;
                const float* rrow = resid ? resid + (size_t)r * N + cbase : (const float*)0;
#pragma unroll
                for (int p = 0; p < 8; p++) {
                    int c = p * 8 + (lane & 3) * 2;
                    float v0 = acc[t][p][half * 2 + 0] + bias[cbase + c];
                    float v1 = acc[t][p][half * 2 + 1] + bias[cbase + c + 1];
                    if (rrow) { v0 += rrow[c]; v1 += rrow[c + 1]; }
                    float2 o; o.x = v0; o.y = v1;
                    *(float2*)(crow + c) = o;
                }
            } else {
                unsigned short* orow = (unsigned short*)Cout + (size_t)r * 2 * N;
#pragma unroll
                for (int p = 0; p < 8; p++) {
                    int c = p * 8 + (lane & 3) * 2;
                    float v0 = gelu_tanh(acc[t][p][half * 2 + 0] + bias[cbase + c]);
                    float v1 = gelu_tanh(acc[t][p][half * 2 + 1] + bias[cbase + c + 1]);
                    unsigned short h0, l0, h1, l1;
                    split_bf16(v0, h0, l0);
                    split_bf16(v1, h1, l1);
                    int cn = cbase + c;
                    *(uint32_t*)(orow + cn)     = (uint32_t)h0 | ((uint32_t)h1 << 16);
                    *(uint32_t*)(orow + N + cn) = (uint32_t)l0 | ((uint32_t)l1 << 16);
                }
            }
        }
    }
}

// ==================== Shifted-window attention -> bf16 pair out ----------------
__device__ __forceinline__ int region_id(int hs, int ws) {
    int rh = (hs < HH - WS) ? 0 : (hs < HH - SHIFT) ? 1 : 2;
    int rw = (ws < WW - WS) ? 0 : (ws < WW - SHIFT) ? 1 : 2;
    return rh * 3 + rw;
}

// 128 threads = 2 heads x 64 queries; qkv combined layout [tok][1536]: q|k|v
__global__ __launch_bounds__(128) void attn_kernel(const float* __restrict__ qkv,
                                                   const float* __restrict__ table,
                                                   unsigned short* __restrict__ out) {
    __shared__ float Ks[2][64 * 32];
    __shared__ float Vs[2][64 * 32];
    __shared__ float T[2][225];

    int bi = blockIdx.x;
    int nhp = bi & 7;  bi >>= 3;
    int nww = bi & 7;  bi >>= 3;
    int nwh = bi & 7;  bi >>= 3;
    int b = bi;
    int tid = threadIdx.x;
    int hs = tid >> 6;
    int t6 = tid & 63;
    int nh = nhp * 2 + hs;

    for (int i = t6; i < 225; i += 64) T[hs][i] = table[i * NHEAD + nh];

    for (int idx = t6; idx < 512; idx += 64) {
        int e = idx >> 3, d4 = (idx & 7) << 2;
        int h = (nwh * WS + (e >> 3) + SHIFT) & (HH - 1);
        int w = (nww * WS + (e & 7) + SHIFT) & (WW - 1);
        size_t tok = ((size_t)b * HH + h) * WW + w;
        float4 kk = *(const float4*)(qkv + tok * (3 * DD) + DD + nh * DK + d4);
        float4 vv = *(const float4*)(qkv + tok * (3 * DD) + 2 * DD + nh * DK + d4);
        *(float4*)(Ks[hs] + e * 32 + d4) = kk;
        *(float4*)(Vs[hs] + e * 32 + d4) = vv;
    }
    __syncthreads();

    int iq = t6 >> 3, jq = t6 & 7;
    int h = (nwh * WS + iq + SHIFT) & (HH - 1);
    int w = (nww * WS + jq + SHIFT) & (WW - 1);
    size_t tok = ((size_t)b * HH + h) * WW + w;

    float qr[DK];
#pragma unroll
    for (int d = 0; d < DK; d += 4)
        *(float4*)(qr + d) = *(const float4*)(qkv + tok * (3 * DD) + nh * DK + d);

    int cq = region_id(nwh * WS + iq, nww * WS + jq);

    float sreg[64];
    float rowmax = -1e30f;
#pragma unroll 4
    for (int k = 0; k < 64; k++) {
        int ik = k >> 3, jk = k & 7;
        float dot = 0.f;
#pragma unroll
        for (int d = 0; d < DK; d++) dot += qr[d] * Ks[hs][k * 32 + d];
        float s = dot * SCALE + T[hs][(iq - ik + 7) * 15 + (jq - jk + 7)];
        int ck = region_id(nwh * WS + ik, nww * WS + jk);
        if (ck != cq) s = -1e9f;
        sreg[k] = s;
        rowmax = fmaxf(rowmax, s);
    }

    float denom = 0.f;
#pragma unroll
    for (int k = 0; k < 64; k++) {
        float e = expf(sreg[k] - rowmax);
        sreg[k] = e;
        denom += e;
    }
    float inv = 1.0f / denom;

    float accv[DK];
#pragma unroll
    for (int d = 0; d < DK; d++) accv[d] = 0.f;
#pragma unroll 4
    for (int k = 0; k < 64; k++) {
        float a = sreg[k];
#pragma unroll
        for (int d = 0; d < DK; d++) accv[d] += a * Vs[hs][k * 32 + d];
    }

    unsigned short* orow = out + tok * 2 * DD + nh * DK;
#pragma unroll
    for (int d = 0; d < DK; d += 2) {
        unsigned short h0, l0, h1, l1;
        split_bf16(accv[d] * inv, h0, l0);
        split_bf16(accv[d + 1] * inv, h1, l1);
        *(uint32_t*)(orow + d)      = (uint32_t)h0 | ((uint32_t)h1 << 16);
        *(uint32_t*)(orow + DD + d) = (uint32_t)l0 | ((uint32_t)l1 << 16);
    }
}

// ==================== driver ===================================================
extern "C" void kernel_launch(void* const* d_in, const int* in_sizes, int n_in,
                              void* d_out, int out_size) {
    const float* x_in      = (const float*)d_in[0];
    const float* Wq        = (const float*)d_in[3];
    const float* bq        = (const float*)d_in[4];
    const float* Wkv       = (const float*)d_in[5];
    const float* bkv       = (const float*)d_in[6];
    const float* Wo        = (const float*)d_in[7];
    const float* bo        = (const float*)d_in[8];
    const float* rel_table = (const float*)d_in[9];
    const float* ln1_g     = (const float*)d_in[10];
    const float* ln1_b     = (const float*)d_in[11];
    const float* ln2_g     = (const float*)d_in[12];
    const float* ln2_b     = (const float*)d_in[13];
    const float* W1        = (const float*)d_in[14];
    const float* b1        = (const float*)d_in[15];
    const float* W2        = (const float*)d_in[16];
    const float* b2        = (const float*)d_in[17];

    float* x = (float*)d_out;

    unsigned short *xn2, *hb2, *ao2, *hid2, *w2;
    float *qkv, *bqkv;
    cudaGetSymbolAddress((void**)&xn2,  g_xn2);
    cudaGetSymbolAddress((void**)&hb2,  g_hb2);
    cudaGetSymbolAddress((void**)&ao2,  g_ao2);
    cudaGetSymbolAddress((void**)&hid2, g_hid2);
    cudaGetSymbolAddress((void**)&w2,   g_w2);
    cudaGetSymbolAddress((void**)&qkv,  g_qkv);
    cudaGetSymbolAddress((void**)&bqkv, g_bqkv);

    cudaFuncSetAttribute(gemm_mma, cudaFuncAttributeMaxDynamicSharedMemorySize, GEMM_SMEM);

    // weight buffer offsets (elements); rows of length 2K
    const size_t off_qkv = 0;                                  // [1536][1024] per layer
    const size_t off_o   = off_qkv + (size_t)LAYERS * 1536 * 1024;
    const size_t off_1   = off_o   + (size_t)LAYERS * 512 * 1024;
    const size_t off_2   = off_1   + (size_t)LAYERS * 2048 * 1024;

    dim3 tb(32, 8);
    // fused QKV weight: rows 0..511 = Wq, rows 512..1535 = Wkv
    convw_kernel<<<dim3(512 / 32,  512 / 32,  LAYERS), tb>>>(Wq,  w2 + off_qkv, 512, 512,
                                                             (size_t)1536 * 1024);
    convw_kernel<<<dim3(1024 / 32, 512 / 32,  LAYERS), tb>>>(Wkv, w2 + off_qkv + (size_t)512 * 1024,
                                                             512, 1024, (size_t)1536 * 1024);
    convw_kernel<<<dim3(512 / 32,  512 / 32,  LAYERS), tb>>>(Wo,  w2 + off_o, 512, 512,
                                                             (size_t)512 * 1024);
    convw_kernel<<<dim3(2048 / 32, 512 / 32,  LAYERS), tb>>>(W1,  w2 + off_1, 512, 2048,
                                                             (size_t)2048 * 1024);
    convw_kernel<<<dim3(512 / 32,  2048 / 32, LAYERS), tb>>>(W2,  w2 + off_2, 2048, 512,
                                                             (size_t)512 * 4096);
    bcat_kernel<<<(LAYERS * 3 * DD + 255) / 256, 256>>>(bq, bkv, bqkv);

    cudaMemcpyAsync(x, x_in, (size_t)TOK * DD * sizeof(float),
                    cudaMemcpyDeviceToDevice, 0);

    for (int l = 0; l < LAYERS; l++) {
        const unsigned short* wqkv_l = w2 + off_qkv + (size_t)l * 1536 * 1024;
        const unsigned short* wo_l   = w2 + off_o   + (size_t)l * 512 * 1024;
        const unsigned short* w1_l   = w2 + off_1   + (size_t)l * 2048 * 1024;
        const unsigned short* w2_l   = w2 + off_2   + (size_t)l * 512 * 4096;
        const float* bqkv_l = bqkv + (size_t)l * 3 * DD;
        const float* bo_l   = bo   + (size_t)l * DD;
        const float* tbl_l  = rel_table + (size_t)l * 225 * NHEAD;
        const float* b1_l   = b1   + (size_t)l * 4 * DD;
        const float* b2_l   = b2   + (size_t)l * DD;

        ln_kernel<<<TOK, 128>>>(x, ln1_g + l * DD, ln1_b + l * DD, xn2);
        gemm_mma<<<dim3(1536 / 128, TOK / 128), 256, GEMM_SMEM>>>(
            xn2, wqkv_l, bqkv_l, nullptr, qkv, 1536, 512, 0);
        attn_kernel<<<BATCH * 8 * 8 * (NHEAD / 2), 128>>>(qkv, tbl_l, ao2);
        gemm_mma<<<dim3(512 / 128, TOK / 128), 256, GEMM_SMEM>>>(
            ao2, wo_l, bo_l, x, x, 512, 512, 0);
        ln_kernel<<<TOK, 128>>>(x, ln2_g + l * DD, ln2_b + l * DD, hb2);
        gemm_mma<<<dim3(2048 / 128, TOK / 128), 256, GEMM_SMEM>>>(
            hb2, w1_l, b1_l, nullptr, hid2, 2048, 512, 1);
        gemm_mma<<<dim3(512 / 128, TOK / 128), 256, GEMM_SMEM>>>(
            hid2, w2_l, b2_l, x, x, 512, 2048, 0);
    }
}

// round 9
// speedup vs baseline: 1.4897x; 1.4897x over previous
#include <cuda_runtime.h>
#include <cuda_fp16.h>
#include <math.h>
#include <stdint.h>

// Problem constants
#define BATCH 8
#define HH 64
#define WW 64
#define DD 512
#define NHEAD 16
#define DK 32
#define WS 8
#define SHIFT 4
#define TOK (BATCH*HH*WW)      // 32768
#define LAYERS 4
#define SCALE 0.17677669529663687f  // 1/sqrt(32)

// -------------------- scratch (allocation-free: __device__ globals) ------------
// fp16 "pair" activations: [hi | lo] along K (row stride 2K)
__device__ __align__(128) __half g_xn2 [ (size_t)TOK * 2 * DD ];       // 64 MB
__device__ __align__(128) __half g_hb2 [ (size_t)TOK * 2 * DD ];       // 64 MB
__device__ __align__(128) __half g_ao2 [ (size_t)TOK * 2 * DD ];       // 64 MB
__device__ __align__(128) __half g_hid2[ (size_t)TOK * 2 * 4 * DD ];   // 256 MB
__device__ __align__(128) __half g_wf  [ 12582912 ];                   // 24 MB, single fp16 [N][K]
__device__ float g_qkv [ (size_t)TOK * 3 * DD ];                       // 201 MB
__device__ float g_bqkv[ LAYERS * 3 * DD ];

// ==================== helpers ==================================================
__device__ __forceinline__ uint32_t smem_u32(const void* p) {
    uint32_t a;
    asm("{ .reg .u64 t; cvta.to.shared.u64 t, %1; cvt.u32.u64 %0, t; }" : "=r"(a) : "l"(p));
    return a;
}
#define CP_ASYNC16(dst, src) \
    asm volatile("cp.async.cg.shared.global [%0], [%1], 16;" :: "r"(dst), "l"(src))
#define CP_COMMIT() asm volatile("cp.async.commit_group;" ::: "memory")
#define CP_WAIT1()  asm volatile("cp.async.wait_group 1;" ::: "memory")
#define CP_WAIT0()  asm volatile("cp.async.wait_group 0;" ::: "memory")

__device__ __forceinline__ void ldmx4(uint32_t& r0, uint32_t& r1, uint32_t& r2, uint32_t& r3,
                                      uint32_t addr) {
    asm volatile("ldmatrix.sync.aligned.m8n8.x4.shared.b16 {%0,%1,%2,%3}, [%4];"
                 : "=r"(r0), "=r"(r1), "=r"(r2), "=r"(r3) : "r"(addr));
}
__device__ __forceinline__ void mma16816(float* d, uint32_t a0, uint32_t a1, uint32_t a2,
                                         uint32_t a3, uint32_t b0, uint32_t b1) {
    asm volatile("mma.sync.aligned.m16n8k16.row.col.f32.f16.f16.f32 "
                 "{%0,%1,%2,%3},{%4,%5,%6,%7},{%8,%9},{%0,%1,%2,%3};"
                 : "+f"(d[0]), "+f"(d[1]), "+f"(d[2]), "+f"(d[3])
                 : "r"(a0), "r"(a1), "r"(a2), "r"(a3), "r"(b0), "r"(b1));
}

__device__ __forceinline__ void split_f16(float v, __half& hi, __half& lo) {
    hi = __float2half_rn(v);
    lo = __float2half_rn(v - __half2float(hi));
}
__device__ __forceinline__ float gelu_tanh(float x) {
    float x3 = x * x * x;
    return 0.5f * x * (1.0f + tanhf(0.7978845608028654f * (x + 0.044715f * x3)));
}

// ==================== weight convert: W[K,N] -> Wf[N,K] fp16 ===================
__global__ void convw_kernel(const float* __restrict__ src, __half* __restrict__ dst,
                             int K, int N, size_t zstride) {
    __shared__ float t[32][33];
    int n0 = blockIdx.x * 32, k0 = blockIdx.y * 32;
    src += (size_t)blockIdx.z * K * N;
    dst += (size_t)blockIdx.z * zstride;
    int tx = threadIdx.x, ty = threadIdx.y;
#pragma unroll
    for (int i = 0; i < 4; i++)
        t[ty + i * 8][tx] = src[(size_t)(k0 + ty + i * 8) * N + n0 + tx];
    __syncthreads();
#pragma unroll
    for (int i = 0; i < 4; i++) {
        int n = n0 + ty + i * 8;
        int k = k0 + tx;
        dst[(size_t)n * K + k] = __float2half_rn(t[tx][ty + i * 8]);
    }
}

// ==================== bias concat for fused QKV ================================
__global__ void bcat_kernel(const float* __restrict__ bq, const float* __restrict__ bkv,
                            float* __restrict__ out) {
    int i = blockIdx.x * 256 + threadIdx.x;
    if (i >= LAYERS * 3 * DD) return;
    int l = i / (3 * DD), c = i % (3 * DD);
    out[i] = (c < DD) ? bq[l * DD + c] : bkv[l * 2 * DD + (c - DD)];
}

// ==================== LayerNorm -> fp16 pair ===================================
__global__ __launch_bounds__(128) void ln_kernel(const float* __restrict__ x,
                                                 const float* __restrict__ gamma,
                                                 const float* __restrict__ beta,
                                                 __half* __restrict__ out) {
    int tok = blockIdx.x;
    int tid = threadIdx.x;
    const float* xr = x + (size_t)tok * DD;
    float v[4];
#pragma unroll
    for (int i = 0; i < 4; i++) v[i] = xr[tid + i * 128];

    __shared__ float s1[4], s2[4];
    int lane = tid & 31, warp = tid >> 5;

    float s = v[0] + v[1] + v[2] + v[3];
#pragma unroll
    for (int o = 16; o > 0; o >>= 1) s += __shfl_xor_sync(0xffffffffu, s, o);
    if (lane == 0) s1[warp] = s;
    __syncthreads();
    float mean = (s1[0] + s1[1] + s1[2] + s1[3]) * (1.0f / DD);

    float sq = 0.f;
#pragma unroll
    for (int i = 0; i < 4; i++) { float d = v[i] - mean; sq += d * d; }
#pragma unroll
    for (int o = 16; o > 0; o >>= 1) sq += __shfl_xor_sync(0xffffffffu, sq, o);
    if (lane == 0) s2[warp] = sq;
    __syncthreads();
    float var = (s2[0] + s2[1] + s2[2] + s2[3]) * (1.0f / DD);
    float rs = rsqrtf(var + 1e-5f);

    __half* orow = out + (size_t)tok * 2 * DD;
#pragma unroll
    for (int i = 0; i < 4; i++) {
        int c = tid + i * 128;
        float o = (v[i] - mean) * rs * gamma[c] + beta[c];
        __half hi, lo;
        split_f16(o, hi, lo);
        orow[c] = hi;
        orow[DD + c] = lo;
    }
}

// ==================== fp16 mma GEMM (2-product split-A schedule) ===============
// C[M,N] = epilogue(A2[M,2K] @ Wf[N,K]^T), schedule: chunks 0..nc1-1 = Ah*W,
// chunks nc1..2nc1-1 = Al*W (B chunk index wraps).
// mode 0: fp32 out (+bias, +optional resid)   mode 1: gelu -> fp16 pair out
#define GBK 64
#define GSTAGES 3
#define GSTAGE_BYTES 32768     // A 16KB + B 16KB
#define GSB_OFF 16384
#define GEMM_SMEM (GSTAGES * GSTAGE_BYTES)

__global__ __launch_bounds__(256, 2) void gemm_mma(const __half* __restrict__ A2,
                                                   const __half* __restrict__ Wf,
                                                   const float* __restrict__ bias,
                                                   const float* __restrict__ resid,
                                                   void* __restrict__ Cout,
                                                   int N, int K, int mode) {
    extern __shared__ char smem[];
    uint32_t sb = smem_u32(smem);
    int tid = threadIdx.x, wid = tid >> 5, lane = tid & 31;
    int bm0 = blockIdx.y * 128, bn0 = blockIdx.x * 128;
    int wm = (wid & 3) * 32, wn = (wid >> 2) * 64;

    float acc[2][8][4];
#pragma unroll
    for (int t = 0; t < 2; t++)
#pragma unroll
        for (int n = 0; n < 8; n++)
#pragma unroll
            for (int r = 0; r < 4; r++) acc[t][n][r] = 0.f;

    const int nc1 = K >> 6;           // B chunks
    const int nch = nc1 * 2;          // total schedule chunks (Ah pass + Al pass)

    // cp.async loader mapping: row = tid>>1 (0..127), 4 x 16B slots at (tid&1)*4
    int lr = tid >> 1;
    int lc0 = (tid & 1) * 4;
    const __half* agp = A2 + (size_t)(bm0 + lr) * (2 * K) + lc0 * 8;
    const __half* bgp = Wf + (size_t)(bn0 + lr) * K + lc0 * 8;
    uint32_t sw[4];
#pragma unroll
    for (int it = 0; it < 4; it++)
        sw[it] = (uint32_t)lr * 128 + (uint32_t)(((lc0 + it) ^ (lr & 7)) << 4);

    // ldmatrix per-warp bases
    int arow[2], arx[2];
#pragma unroll
    for (int t = 0; t < 2; t++) {
        int r = wm + t * 16 + (lane & 15);
        arow[t] = r * 128;
        arx[t] = r & 7;
    }
    int ach = lane >> 4;
    int brow[4], brx[4];
#pragma unroll
    for (int p = 0; p < 4; p++) {
        int n = wn + p * 16 + (lane & 7) + ((lane >> 4) << 3);
        brow[p] = n * 128;
        brx[p] = n & 7;
    }
    int bch = (lane >> 3) & 1;

    // stage issue (B chunk wraps for the Al pass)
    auto issue_stage = [&](int c, int stage) {
        uint32_t st = sb + (uint32_t)stage * GSTAGE_BYTES;
        int cb = (c < nc1) ? c : c - nc1;
        const __half* ag = agp + (size_t)c * GBK;
        const __half* bg = bgp + (size_t)cb * GBK;
#pragma unroll
        for (int it = 0; it < 4; it++) CP_ASYNC16(st + sw[it], ag + it * 8);
#pragma unroll
        for (int it = 0; it < 4; it++) CP_ASYNC16(st + GSB_OFF + sw[it], bg + it * 8);
        CP_COMMIT();
    };

    issue_stage(0, 0);
    issue_stage(1, 1);

    int buf = 0, nbuf = 2;
    for (int c = 0; c < nch; c++) {
        if (c == nch - 1) { CP_WAIT0(); } else { CP_WAIT1(); }
        __syncthreads();
        if (c + 2 < nch) issue_stage(c + 2, nbuf);

        uint32_t stA = sb + (uint32_t)buf * GSTAGE_BYTES;
        uint32_t stB = stA + GSB_OFF;
#pragma unroll
        for (int ks = 0; ks < 4; ks++) {
            uint32_t a0[4], a1[4];
            {
                uint32_t ad0 = stA + arow[0] + (uint32_t)((((ks << 1) + ach) ^ arx[0]) << 4);
                ldmx4(a0[0], a0[1], a0[2], a0[3], ad0);
                uint32_t ad1 = stA + arow[1] + (uint32_t)((((ks << 1) + ach) ^ arx[1]) << 4);
                ldmx4(a1[0], a1[1], a1[2], a1[3], ad1);
            }
#pragma unroll
            for (int p = 0; p < 4; p++) {
                uint32_t b0, b1, b2, b3;
                uint32_t bd = stB + brow[p] + (uint32_t)((((ks << 1) + bch) ^ brx[p]) << 4);
                ldmx4(b0, b1, b2, b3, bd);
                mma16816(acc[0][2 * p],     a0[0], a0[1], a0[2], a0[3], b0, b1);
                mma16816(acc[0][2 * p + 1], a0[0], a0[1], a0[2], a0[3], b2, b3);
                mma16816(acc[1][2 * p],     a1[0], a1[1], a1[2], a1[3], b0, b1);
                mma16816(acc[1][2 * p + 1], a1[0], a1[1], a1[2], a1[3], b2, b3);
            }
        }
        buf = (buf + 1 == GSTAGES) ? 0 : buf + 1;
        nbuf = (nbuf + 1 == GSTAGES) ? 0 : nbuf + 1;
        __syncthreads();
    }

    // epilogue
    int cbase = bn0 + wn;
#pragma unroll
    for (int t = 0; t < 2; t++) {
        int r0 = bm0 + wm + t * 16 + (lane >> 2);
#pragma unroll
        for (int half = 0; half < 2; half++) {
            int r = r0 + half * 8;
            if (mode == 0) {
                float* crow = (float*)Cout + (size_t)r * N + cbase;
                const float* rrow = resid ? resid + (size_t)r * N + cbase : (const float*)0;
#pragma unroll
                for (int p = 0; p < 8; p++) {
                    int c = p * 8 + (lane & 3) * 2;
                    float v0 = acc[t][p][half * 2 + 0] + bias[cbase + c];
                    float v1 = acc[t][p][half * 2 + 1] + bias[cbase + c + 1];
                    if (rrow) { v0 += rrow[c]; v1 += rrow[c + 1]; }
                    float2 o; o.x = v0; o.y = v1;
                    *(float2*)(crow + c) = o;
                }
            } else {
                __half* orow = (__half*)Cout + (size_t)r * 2 * N;
#pragma unroll
                for (int p = 0; p < 8; p++) {
                    int c = p * 8 + (lane & 3) * 2;
                    float v0 = gelu_tanh(acc[t][p][half * 2 + 0] + bias[cbase + c]);
                    float v1 = gelu_tanh(acc[t][p][half * 2 + 1] + bias[cbase + c + 1]);
                    __half h0, l0, h1, l1;
                    split_f16(v0, h0, l0);
                    split_f16(v1, h1, l1);
                    int cn = cbase + c;
                    *(uint32_t*)(orow + cn)     = (uint32_t)__half_as_ushort(h0) |
                                                  ((uint32_t)__half_as_ushort(h1) << 16);
                    *(uint32_t*)(orow + N + cn) = (uint32_t)__half_as_ushort(l0) |
                                                  ((uint32_t)__half_as_ushort(l1) << 16);
                }
            }
        }
    }
}

// ==================== Shifted-window attention -> fp16 pair out ----------------
__device__ __forceinline__ int region_id(int hs, int ws) {
    int rh = (hs < HH - WS) ? 0 : (hs < HH - SHIFT) ? 1 : 2;
    int rw = (ws < WW - WS) ? 0 : (ws < WW - SHIFT) ? 1 : 2;
    return rh * 3 + rw;
}

// 128 threads = 2 heads x 64 queries; qkv combined layout [tok][1536]: q|k|v
__global__ __launch_bounds__(128) void attn_kernel(const float* __restrict__ qkv,
                                                   const float* __restrict__ table,
                                                   __half* __restrict__ out) {
    __shared__ float Ks[2][64 * 32];
    __shared__ float Vs[2][64 * 32];
    __shared__ float T[2][225];

    int bi = blockIdx.x;
    int nhp = bi & 7;  bi >>= 3;
    int nww = bi & 7;  bi >>= 3;
    int nwh = bi & 7;  bi >>= 3;
    int b = bi;
    int tid = threadIdx.x;
    int hs = tid >> 6;
    int t6 = tid & 63;
    int nh = nhp * 2 + hs;

    for (int i = t6; i < 225; i += 64) T[hs][i] = table[i * NHEAD + nh];

    for (int idx = t6; idx < 512; idx += 64) {
        int e = idx >> 3, d4 = (idx & 7) << 2;
        int h = (nwh * WS + (e >> 3) + SHIFT) & (HH - 1);
        int w = (nww * WS + (e & 7) + SHIFT) & (WW - 1);
        size_t tok = ((size_t)b * HH + h) * WW + w;
        float4 kk = *(const float4*)(qkv + tok * (3 * DD) + DD + nh * DK + d4);
        float4 vv = *(const float4*)(qkv + tok * (3 * DD) + 2 * DD + nh * DK + d4);
        *(float4*)(Ks[hs] + e * 32 + d4) = kk;
        *(float4*)(Vs[hs] + e * 32 + d4) = vv;
    }
    __syncthreads();

    int iq = t6 >> 3, jq = t6 & 7;
    int h = (nwh * WS + iq + SHIFT) & (HH - 1);
    int w = (nww * WS + jq + SHIFT) & (WW - 1);
    size_t tok = ((size_t)b * HH + h) * WW + w;

    float qr[DK];
#pragma unroll
    for (int d = 0; d < DK; d += 4)
        *(float4*)(qr + d) = *(const float4*)(qkv + tok * (3 * DD) + nh * DK + d);

    int cq = region_id(nwh * WS + iq, nww * WS + jq);

    float sreg[64];
    float rowmax = -1e30f;
#pragma unroll 4
    for (int k = 0; k < 64; k++) {
        int ik = k >> 3, jk = k & 7;
        float dot = 0.f;
#pragma unroll
        for (int d = 0; d < DK; d++) dot += qr[d] * Ks[hs][k * 32 + d];
        float s = dot * SCALE + T[hs][(iq - ik + 7) * 15 + (jq - jk + 7)];
        int ck = region_id(nwh * WS + ik, nww * WS + jk);
        if (ck != cq) s = -1e9f;
        sreg[k] = s;
        rowmax = fmaxf(rowmax, s);
    }

    float denom = 0.f;
#pragma unroll
    for (int k = 0; k < 64; k++) {
        float e = expf(sreg[k] - rowmax);
        sreg[k] = e;
        denom += e;
    }
    float inv = 1.0f / denom;

    float accv[DK];
#pragma unroll
    for (int d = 0; d < DK; d++) accv[d] = 0.f;
#pragma unroll 4
    for (int k = 0; k < 64; k++) {
        float a = sreg[k];
#pragma unroll
        for (int d = 0; d < DK; d++) accv[d] += a * Vs[hs][k * 32 + d];
    }

    __half* orow = out + tok * 2 * DD + nh * DK;
#pragma unroll
    for (int d = 0; d < DK; d += 2) {
        __half h0, l0, h1, l1;
        split_f16(accv[d] * inv, h0, l0);
        split_f16(accv[d + 1] * inv, h1, l1);
        *(uint32_t*)(orow + d)      = (uint32_t)__half_as_ushort(h0) |
                                      ((uint32_t)__half_as_ushort(h1) << 16);
        *(uint32_t*)(orow + DD + d) = (uint32_t)__half_as_ushort(l0) |
                                      ((uint32_t)__half_as_ushort(l1) << 16);
    }
}

// ==================== driver ===================================================
extern "C" void kernel_launch(void* const* d_in, const int* in_sizes, int n_in,
                              void* d_out, int out_size) {
    const float* x_in      = (const float*)d_in[0];
    const float* Wq        = (const float*)d_in[3];
    const float* bq        = (const float*)d_in[4];
    const float* Wkv       = (const float*)d_in[5];
    const float* bkv       = (const float*)d_in[6];
    const float* Wo        = (const float*)d_in[7];
    const float* bo        = (const float*)d_in[8];
    const float* rel_table = (const float*)d_in[9];
    const float* ln1_g     = (const float*)d_in[10];
    const float* ln1_b     = (const float*)d_in[11];
    const float* ln2_g     = (const float*)d_in[12];
    const float* ln2_b     = (const float*)d_in[13];
    const float* W1        = (const float*)d_in[14];
    const float* b1        = (const float*)d_in[15];
    const float* W2        = (const float*)d_in[16];
    const float* b2        = (const float*)d_in[17];

    float* x = (float*)d_out;

    __half *xn2, *hb2, *ao2, *hid2, *wf;
    float *qkv, *bqkv;
    cudaGetSymbolAddress((void**)&xn2,  g_xn2);
    cudaGetSymbolAddress((void**)&hb2,  g_hb2);
    cudaGetSymbolAddress((void**)&ao2,  g_ao2);
    cudaGetSymbolAddress((void**)&hid2, g_hid2);
    cudaGetSymbolAddress((void**)&wf,   g_wf);
    cudaGetSymbolAddress((void**)&qkv,  g_qkv);
    cudaGetSymbolAddress((void**)&bqkv, g_bqkv);

    cudaFuncSetAttribute(gemm_mma, cudaFuncAttributeMaxDynamicSharedMemorySize, GEMM_SMEM);

    // weight buffer offsets (elements); rows of length K
    const size_t off_qkv = 0;                                   // [1536][512] per layer
    const size_t off_o   = off_qkv + (size_t)LAYERS * 1536 * 512;
    const size_t off_1   = off_o   + (size_t)LAYERS * 512 * 512;
    const size_t off_2   = off_1   + (size_t)LAYERS * 2048 * 512;

    dim3 tb(32, 8);
    // fused QKV weight: rows 0..511 = Wq, rows 512..1535 = Wkv
    convw_kernel<<<dim3(512 / 32,  512 / 32,  LAYERS), tb>>>(Wq,  wf + off_qkv, 512, 512,
                                                             (size_t)1536 * 512);
    convw_kernel<<<dim3(1024 / 32, 512 / 32,  LAYERS), tb>>>(Wkv, wf + off_qkv + (size_t)512 * 512,
                                                             512, 1024, (size_t)1536 * 512);
    convw_kernel<<<dim3(512 / 32,  512 / 32,  LAYERS), tb>>>(Wo,  wf + off_o, 512, 512,
                                                             (size_t)512 * 512);
    convw_kernel<<<dim3(2048 / 32, 512 / 32,  LAYERS), tb>>>(W1,  wf + off_1, 512, 2048,
                                                             (size_t)2048 * 512);
    convw_kernel<<<dim3(512 / 32,  2048 / 32, LAYERS), tb>>>(W2,  wf + off_2, 2048, 512,
                                                             (size_t)512 * 2048);
    bcat_kernel<<<(LAYERS * 3 * DD + 255) / 256, 256>>>(bq, bkv, bqkv);

    cudaMemcpyAsync(x, x_in, (size_t)TOK * DD * sizeof(float),
                    cudaMemcpyDeviceToDevice, 0);

    for (int l = 0; l < LAYERS; l++) {
        const __half* wqkv_l = wf + off_qkv + (size_t)l * 1536 * 512;
        const __half* wo_l   = wf + off_o   + (size_t)l * 512 * 512;
        const __half* w1_l   = wf + off_1   + (size_t)l * 2048 * 512;
        const __half* w2_l   = wf + off_2   + (size_t)l * 512 * 2048;
        const float* bqkv_l = bqkv + (size_t)l * 3 * DD;
        const float* bo_l   = bo   + (size_t)l * DD;
        const float* tbl_l  = rel_table + (size_t)l * 225 * NHEAD;
        const float* b1_l   = b1   + (size_t)l * 4 * DD;
        const float* b2_l   = b2   + (size_t)l * DD;

        ln_kernel<<<TOK, 128>>>(x, ln1_g + l * DD, ln1_b + l * DD, xn2);
        gemm_mma<<<dim3(1536 / 128, TOK / 128), 256, GEMM_SMEM>>>(
            xn2, wqkv_l, bqkv_l, nullptr, qkv, 1536, 512, 0);
        attn_kernel<<<BATCH * 8 * 8 * (NHEAD / 2), 128>>>(qkv, tbl_l, ao2);
        gemm_mma<<<dim3(512 / 128, TOK / 128), 256, GEMM_SMEM>>>(
            ao2, wo_l, bo_l, x, x, 512, 512, 0);
        ln_kernel<<<TOK, 128>>>(x, ln2_g + l * DD, ln2_b + l * DD, hb2);
        gemm_mma<<<dim3(2048 / 128, TOK / 128), 256, GEMM_SMEM>>>(
            hb2, w1_l, b1_l, nullptr, hid2, 2048, 512, 1);
        gemm_mma<<<dim3(512 / 128, TOK / 128), 256, GEMM_SMEM>>>(
            hid2, w2_l, b2_l, x, x, 512, 2048, 0);
    }
}

// round 10
// speedup vs baseline: 2.5059x; 1.6821x over previous
#include <cuda_runtime.h>
#include <cuda_fp16.h>
#include <math.h>
#include <stdint.h>

// Problem constants
#define BATCH 8
#define HH 64
#define WW 64
#define DD 512
#define NHEAD 16
#define DK 32
#define WS 8
#define SHIFT 4
#define TOK (BATCH*HH*WW)      // 32768
#define LAYERS 4
#define SCALE 0.17677669529663687f  // 1/sqrt(32)

// -------------------- scratch (allocation-free: __device__ globals) ------------
// single fp16 activations, row stride K
__device__ __align__(128) __half g_xn  [ (size_t)TOK * DD ];       // 32 MB
__device__ __align__(128) __half g_hb  [ (size_t)TOK * DD ];       // 32 MB
__device__ __align__(128) __half g_ao  [ (size_t)TOK * DD ];       // 32 MB
__device__ __align__(128) __half g_hid [ (size_t)TOK * 4 * DD ];   // 128 MB
__device__ __align__(128) __half g_wf  [ 12582912 ];               // 24 MB, fp16 [N][K]
__device__ float g_qkv [ (size_t)TOK * 3 * DD ];                   // 201 MB
__device__ float g_bqkv[ LAYERS * 3 * DD ];

// ==================== helpers ==================================================
__device__ __forceinline__ uint32_t smem_u32(const void* p) {
    uint32_t a;
    asm("{ .reg .u64 t; cvta.to.shared.u64 t, %1; cvt.u32.u64 %0, t; }" : "=r"(a) : "l"(p));
    return a;
}
#define CP_ASYNC16(dst, src) \
    asm volatile("cp.async.cg.shared.global [%0], [%1], 16;" :: "r"(dst), "l"(src))
#define CP_COMMIT() asm volatile("cp.async.commit_group;" ::: "memory")
#define CP_WAIT1()  asm volatile("cp.async.wait_group 1;" ::: "memory")
#define CP_WAIT0()  asm volatile("cp.async.wait_group 0;" ::: "memory")

__device__ __forceinline__ void ldmx4(uint32_t& r0, uint32_t& r1, uint32_t& r2, uint32_t& r3,
                                      uint32_t addr) {
    asm volatile("ldmatrix.sync.aligned.m8n8.x4.shared.b16 {%0,%1,%2,%3}, [%4];"
                 : "=r"(r0), "=r"(r1), "=r"(r2), "=r"(r3) : "r"(addr));
}
__device__ __forceinline__ void mma16816(float* d, uint32_t a0, uint32_t a1, uint32_t a2,
                                         uint32_t a3, uint32_t b0, uint32_t b1) {
    asm volatile("mma.sync.aligned.m16n8k16.row.col.f32.f16.f16.f32 "
                 "{%0,%1,%2,%3},{%4,%5,%6,%7},{%8,%9},{%0,%1,%2,%3};"
                 : "+f"(d[0]), "+f"(d[1]), "+f"(d[2]), "+f"(d[3])
                 : "r"(a0), "r"(a1), "r"(a2), "r"(a3), "r"(b0), "r"(b1));
}

__device__ __forceinline__ float gelu_tanh(float x) {
    float x3 = x * x * x;
    return 0.5f * x * (1.0f + tanhf(0.7978845608028654f * (x + 0.044715f * x3)));
}

// ==================== weight convert: W[K,N] -> Wf[N,K] fp16 ===================
__global__ void convw_kernel(const float* __restrict__ src, __half* __restrict__ dst,
                             int K, int N, size_t zstride) {
    __shared__ float t[32][33];
    int n0 = blockIdx.x * 32, k0 = blockIdx.y * 32;
    src += (size_t)blockIdx.z * K * N;
    dst += (size_t)blockIdx.z * zstride;
    int tx = threadIdx.x, ty = threadIdx.y;
#pragma unroll
    for (int i = 0; i < 4; i++)
        t[ty + i * 8][tx] = src[(size_t)(k0 + ty + i * 8) * N + n0 + tx];
    __syncthreads();
#pragma unroll
    for (int i = 0; i < 4; i++) {
        int n = n0 + ty + i * 8;
        int k = k0 + tx;
        dst[(size_t)n * K + k] = __float2half_rn(t[tx][ty + i * 8]);
    }
}

// ==================== bias concat for fused QKV ================================
__global__ void bcat_kernel(const float* __restrict__ bq, const float* __restrict__ bkv,
                            float* __restrict__ out) {
    int i = blockIdx.x * 256 + threadIdx.x;
    if (i >= LAYERS * 3 * DD) return;
    int l = i / (3 * DD), c = i % (3 * DD);
    out[i] = (c < DD) ? bq[l * DD + c] : bkv[l * 2 * DD + (c - DD)];
}

// ==================== LayerNorm -> fp16 ========================================
__global__ __launch_bounds__(128) void ln_kernel(const float* __restrict__ x,
                                                 const float* __restrict__ gamma,
                                                 const float* __restrict__ beta,
                                                 __half* __restrict__ out) {
    int tok = blockIdx.x;
    int tid = threadIdx.x;
    const float* xr = x + (size_t)tok * DD;
    float v[4];
#pragma unroll
    for (int i = 0; i < 4; i++) v[i] = xr[tid + i * 128];

    __shared__ float s1[4], s2[4];
    int lane = tid & 31, warp = tid >> 5;

    float s = v[0] + v[1] + v[2] + v[3];
#pragma unroll
    for (int o = 16; o > 0; o >>= 1) s += __shfl_xor_sync(0xffffffffu, s, o);
    if (lane == 0) s1[warp] = s;
    __syncthreads();
    float mean = (s1[0] + s1[1] + s1[2] + s1[3]) * (1.0f / DD);

    float sq = 0.f;
#pragma unroll
    for (int i = 0; i < 4; i++) { float d = v[i] - mean; sq += d * d; }
#pragma unroll
    for (int o = 16; o > 0; o >>= 1) sq += __shfl_xor_sync(0xffffffffu, sq, o);
    if (lane == 0) s2[warp] = sq;
    __syncthreads();
    float var = (s2[0] + s2[1] + s2[2] + s2[3]) * (1.0f / DD);
    float rs = rsqrtf(var + 1e-5f);

    __half* orow = out + (size_t)tok * DD;
#pragma unroll
    for (int i = 0; i < 4; i++) {
        int c = tid + i * 128;
        orow[c] = __float2half_rn((v[i] - mean) * rs * gamma[c] + beta[c]);
    }
}

// ==================== fp16 mma GEMM (single pass) ==============================
// C[M,N] = epilogue(A[M,K] @ Wf[N,K]^T)
// mode 0: fp32 out (+bias, +optional resid)   mode 1: gelu -> fp16 out
#define GBK 64
#define GSTAGES 3
#define GSTAGE_BYTES 32768     // A 16KB + B 16KB
#define GSB_OFF 16384
#define GEMM_SMEM (GSTAGES * GSTAGE_BYTES)

__global__ __launch_bounds__(256, 2) void gemm_mma(const __half* __restrict__ A,
                                                   const __half* __restrict__ Wf,
                                                   const float* __restrict__ bias,
                                                   const float* __restrict__ resid,
                                                   void* __restrict__ Cout,
                                                   int N, int K, int mode) {
    extern __shared__ char smem[];
    uint32_t sb = smem_u32(smem);
    int tid = threadIdx.x, wid = tid >> 5, lane = tid & 31;
    int bm0 = blockIdx.y * 128, bn0 = blockIdx.x * 128;
    int wm = (wid & 3) * 32, wn = (wid >> 2) * 64;

    float acc[2][8][4];
#pragma unroll
    for (int t = 0; t < 2; t++)
#pragma unroll
        for (int n = 0; n < 8; n++)
#pragma unroll
            for (int r = 0; r < 4; r++) acc[t][n][r] = 0.f;

    const int nch = K >> 6;

    // cp.async loader mapping: row = tid>>1 (0..127), 4 x 16B slots at (tid&1)*4
    int lr = tid >> 1;
    int lc0 = (tid & 1) * 4;
    const __half* agp = A + (size_t)(bm0 + lr) * K + lc0 * 8;
    const __half* bgp = Wf + (size_t)(bn0 + lr) * K + lc0 * 8;
    uint32_t sw[4];
#pragma unroll
    for (int it = 0; it < 4; it++)
        sw[it] = (uint32_t)lr * 128 + (uint32_t)(((lc0 + it) ^ (lr & 7)) << 4);

    // ldmatrix per-warp bases
    int arow[2], arx[2];
#pragma unroll
    for (int t = 0; t < 2; t++) {
        int r = wm + t * 16 + (lane & 15);
        arow[t] = r * 128;
        arx[t] = r & 7;
    }
    int ach = lane >> 4;
    int brow[4], brx[4];
#pragma unroll
    for (int p = 0; p < 4; p++) {
        int n = wn + p * 16 + (lane & 7) + ((lane >> 4) << 3);
        brow[p] = n * 128;
        brx[p] = n & 7;
    }
    int bch = (lane >> 3) & 1;

    auto issue_stage = [&](int c, int stage) {
        uint32_t st = sb + (uint32_t)stage * GSTAGE_BYTES;
        const __half* ag = agp + (size_t)c * GBK;
        const __half* bg = bgp + (size_t)c * GBK;
#pragma unroll
        for (int it = 0; it < 4; it++) CP_ASYNC16(st + sw[it], ag + it * 8);
#pragma unroll
        for (int it = 0; it < 4; it++) CP_ASYNC16(st + GSB_OFF + sw[it], bg + it * 8);
        CP_COMMIT();
    };

    issue_stage(0, 0);
    issue_stage(1, 1);

    int buf = 0, nbuf = 2;
    for (int c = 0; c < nch; c++) {
        if (c == nch - 1) { CP_WAIT0(); } else { CP_WAIT1(); }
        __syncthreads();
        if (c + 2 < nch) issue_stage(c + 2, nbuf);

        uint32_t stA = sb + (uint32_t)buf * GSTAGE_BYTES;
        uint32_t stB = stA + GSB_OFF;
#pragma unroll
        for (int ks = 0; ks < 4; ks++) {
            uint32_t a0[4], a1[4];
            {
                uint32_t ad0 = stA + arow[0] + (uint32_t)((((ks << 1) + ach) ^ arx[0]) << 4);
                ldmx4(a0[0], a0[1], a0[2], a0[3], ad0);
                uint32_t ad1 = stA + arow[1] + (uint32_t)((((ks << 1) + ach) ^ arx[1]) << 4);
                ldmx4(a1[0], a1[1], a1[2], a1[3], ad1);
            }
#pragma unroll
            for (int p = 0; p < 4; p++) {
                uint32_t b0, b1, b2, b3;
                uint32_t bd = stB + brow[p] + (uint32_t)((((ks << 1) + bch) ^ brx[p]) << 4);
                ldmx4(b0, b1, b2, b3, bd);
                mma16816(acc[0][2 * p],     a0[0], a0[1], a0[2], a0[3], b0, b1);
                mma16816(acc[0][2 * p + 1], a0[0], a0[1], a0[2], a0[3], b2, b3);
                mma16816(acc[1][2 * p],     a1[0], a1[1], a1[2], a1[3], b0, b1);
                mma16816(acc[1][2 * p + 1], a1[0], a1[1], a1[2], a1[3], b2, b3);
            }
        }
        buf = (buf + 1 == GSTAGES) ? 0 : buf + 1;
        nbuf = (nbuf + 1 == GSTAGES) ? 0 : nbuf + 1;
        __syncthreads();
    }

    // epilogue
    int cbase = bn0 + wn;
#pragma unroll
    for (int t = 0; t < 2; t++) {
        int r0 = bm0 + wm + t * 16 + (lane >> 2);
#pragma unroll
        for (int half = 0; half < 2; half++) {
            int r = r0 + half * 8;
            if (mode == 0) {
                float* crow = (float*)Cout + (size_t)r * N + cbase;
                const float* rrow = resid ? resid + (size_t)r * N + cbase : (const float*)0;
#pragma unroll
                for (int p = 0; p < 8; p++) {
                    int c = p * 8 + (lane & 3) * 2;
                    float v0 = acc[t][p][half * 2 + 0] + bias[cbase + c];
                    float v1 = acc[t][p][half * 2 + 1] + bias[cbase + c + 1];
                    if (rrow) { v0 += rrow[c]; v1 += rrow[c + 1]; }
                    float2 o; o.x = v0; o.y = v1;
                    *(float2*)(crow + c) = o;
                }
            } else {
                __half* orow = (__half*)Cout + (size_t)r * N;
#pragma unroll
                for (int p = 0; p < 8; p++) {
                    int c = p * 8 + (lane & 3) * 2;
                    float v0 = gelu_tanh(acc[t][p][half * 2 + 0] + bias[cbase + c]);
                    float v1 = gelu_tanh(acc[t][p][half * 2 + 1] + bias[cbase + c + 1]);
                    int cn = cbase + c;
                    *(uint32_t*)(orow + cn) =
                        (uint32_t)__half_as_ushort(__float2half_rn(v0)) |
                        ((uint32_t)__half_as_ushort(__float2half_rn(v1)) << 16);
                }
            }
        }
    }
}

// ==================== Shifted-window attention -> fp16 out ---------------------
__device__ __forceinline__ int region_id(int hs, int ws) {
    int rh = (hs < HH - WS) ? 0 : (hs < HH - SHIFT) ? 1 : 2;
    int rw = (ws < WW - WS) ? 0 : (ws < WW - SHIFT) ? 1 : 2;
    return rh * 3 + rw;
}

// 128 threads = 2 heads x 64 queries; qkv combined layout [tok][1536]: q|k|v
__global__ __launch_bounds__(128) void attn_kernel(const float* __restrict__ qkv,
                                                   const float* __restrict__ table,
                                                   __half* __restrict__ out) {
    __shared__ float Ks[2][64 * 32];
    __shared__ float Vs[2][64 * 32];
    __shared__ float T[2][225];

    int bi = blockIdx.x;
    int nhp = bi & 7;  bi >>= 3;
    int nww = bi & 7;  bi >>= 3;
    int nwh = bi & 7;  bi >>= 3;
    int b = bi;
    int tid = threadIdx.x;
    int hs = tid >> 6;
    int t6 = tid & 63;
    int nh = nhp * 2 + hs;

    for (int i = t6; i < 225; i += 64) T[hs][i] = table[i * NHEAD + nh];

    for (int idx = t6; idx < 512; idx += 64) {
        int e = idx >> 3, d4 = (idx & 7) << 2;
        int h = (nwh * WS + (e >> 3) + SHIFT) & (HH - 1);
        int w = (nww * WS + (e & 7) + SHIFT) & (WW - 1);
        size_t tok = ((size_t)b * HH + h) * WW + w;
        float4 kk = *(const float4*)(qkv + tok * (3 * DD) + DD + nh * DK + d4);
        float4 vv = *(const float4*)(qkv + tok * (3 * DD) + 2 * DD + nh * DK + d4);
        *(float4*)(Ks[hs] + e * 32 + d4) = kk;
        *(float4*)(Vs[hs] + e * 32 + d4) = vv;
    }
    __syncthreads();

    int iq = t6 >> 3, jq = t6 & 7;
    int h = (nwh * WS + iq + SHIFT) & (HH - 1);
    int w = (nww * WS + jq + SHIFT) & (WW - 1);
    size_t tok = ((size_t)b * HH + h) * WW + w;

    float qr[DK];
#pragma unroll
    for (int d = 0; d < DK; d += 4)
        *(float4*)(qr + d) = *(const float4*)(qkv + tok * (3 * DD) + nh * DK + d);

    int cq = region_id(nwh * WS + iq, nww * WS + jq);

    float sreg[64];
    float rowmax = -1e30f;
#pragma unroll 4
    for (int k = 0; k < 64; k++) {
        int ik = k >> 3, jk = k & 7;
        float dot = 0.f;
#pragma unroll
        for (int d = 0; d < DK; d++) dot += qr[d] * Ks[hs][k * 32 + d];
        float s = dot * SCALE + T[hs][(iq - ik + 7) * 15 + (jq - jk + 7)];
        int ck = region_id(nwh * WS + ik, nww * WS + jk);
        if (ck != cq) s = -1e9f;
        sreg[k] = s;
        rowmax = fmaxf(rowmax, s);
    }

    float denom = 0.f;
#pragma unroll
    for (int k = 0; k < 64; k++) {
        float e = expf(sreg[k] - rowmax);
        sreg[k] = e;
        denom += e;
    }
    float inv = 1.0f / denom;

    float accv[DK];
#pragma unroll
    for (int d = 0; d < DK; d++) accv[d] = 0.f;
#pragma unroll 4
    for (int k = 0; k < 64; k++) {
        float a = sreg[k];
#pragma unroll
        for (int d = 0; d < DK; d++) accv[d] += a * Vs[hs][k * 32 + d];
    }

    __half* orow = out + tok * DD + nh * DK;
#pragma unroll
    for (int d = 0; d < DK; d += 2) {
        *(uint32_t*)(orow + d) =
            (uint32_t)__half_as_ushort(__float2half_rn(accv[d] * inv)) |
            ((uint32_t)__half_as_ushort(__float2half_rn(accv[d + 1] * inv)) << 16);
    }
}

// ==================== driver ===================================================
extern "C" void kernel_launch(void* const* d_in, const int* in_sizes, int n_in,
                              void* d_out, int out_size) {
    const float* x_in      = (const float*)d_in[0];
    const float* Wq        = (const float*)d_in[3];
    const float* bq        = (const float*)d_in[4];
    const float* Wkv       = (const float*)d_in[5];
    const float* bkv       = (const float*)d_in[6];
    const float* Wo        = (const float*)d_in[7];
    const float* bo        = (const float*)d_in[8];
    const float* rel_table = (const float*)d_in[9];
    const float* ln1_g     = (const float*)d_in[10];
    const float* ln1_b     = (const float*)d_in[11];
    const float* ln2_g     = (const float*)d_in[12];
    const float* ln2_b     = (const float*)d_in[13];
    const float* W1        = (const float*)d_in[14];
    const float* b1        = (const float*)d_in[15];
    const float* W2        = (const float*)d_in[16];
    const float* b2        = (const float*)d_in[17];

    float* x = (float*)d_out;

    __half *xn, *hb, *ao, *hid, *wf;
    float *qkv, *bqkv;
    cudaGetSymbolAddress((void**)&xn,   g_xn);
    cudaGetSymbolAddress((void**)&hb,   g_hb);
    cudaGetSymbolAddress((void**)&ao,   g_ao);
    cudaGetSymbolAddress((void**)&hid,  g_hid);
    cudaGetSymbolAddress((void**)&wf,   g_wf);
    cudaGetSymbolAddress((void**)&qkv,  g_qkv);
    cudaGetSymbolAddress((void**)&bqkv, g_bqkv);

    cudaFuncSetAttribute(gemm_mma, cudaFuncAttributeMaxDynamicSharedMemorySize, GEMM_SMEM);

    // weight buffer offsets (elements); rows of length K
    const size_t off_qkv = 0;                                   // [1536][512] per layer
    const size_t off_o   = off_qkv + (size_t)LAYERS * 1536 * 512;
    const size_t off_1   = off_o   + (size_t)LAYERS * 512 * 512;
    const size_t off_2   = off_1   + (size_t)LAYERS * 2048 * 512;

    dim3 tb(32, 8);
    // fused QKV weight: rows 0..511 = Wq, rows 512..1535 = Wkv
    convw_kernel<<<dim3(512 / 32,  512 / 32,  LAYERS), tb>>>(Wq,  wf + off_qkv, 512, 512,
                                                             (size_t)1536 * 512);
    convw_kernel<<<dim3(1024 / 32, 512 / 32,  LAYERS), tb>>>(Wkv, wf + off_qkv + (size_t)512 * 512,
                                                             512, 1024, (size_t)1536 * 512);
    convw_kernel<<<dim3(512 / 32,  512 / 32,  LAYERS), tb>>>(Wo,  wf + off_o, 512, 512,
                                                             (size_t)512 * 512);
    convw_kernel<<<dim3(2048 / 32, 512 / 32,  LAYERS), tb>>>(W1,  wf + off_1, 512, 2048,
                                                             (size_t)2048 * 512);
    convw_kernel<<<dim3(512 / 32,  2048 / 32, LAYERS), tb>>>(W2,  wf + off_2, 2048, 512,
                                                             (size_t)512 * 2048);
    bcat_kernel<<<(LAYERS * 3 * DD + 255) / 256, 256>>>(bq, bkv, bqkv);

    cudaMemcpyAsync(x, x_in, (size_t)TOK * DD * sizeof(float),
                    cudaMemcpyDeviceToDevice, 0);

    for (int l = 0; l < LAYERS; l++) {
        const __half* wqkv_l = wf + off_qkv + (size_t)l * 1536 * 512;
        const __half* wo_l   = wf + off_o   + (size_t)l * 512 * 512;
        const __half* w1_l   = wf + off_1   + (size_t)l * 2048 * 512;
        const __half* w2_l   = wf + off_2   + (size_t)l * 512 * 2048;
        const float* bqkv_l = bqkv + (size_t)l * 3 * DD;
        const float* bo_l   = bo   + (size_t)l * DD;
        const float* tbl_l  = rel_table + (size_t)l * 225 * NHEAD;
        const float* b1_l   = b1   + (size_t)l * 4 * DD;
        const float* b2_l   = b2   + (size_t)l * DD;

        ln_kernel<<<TOK, 128>>>(x, ln1_g + l * DD, ln1_b + l * DD, xn);
        gemm_mma<<<dim3(1536 / 128, TOK / 128), 256, GEMM_SMEM>>>(
            xn, wqkv_l, bqkv_l, nullptr, qkv, 1536, 512, 0);
        attn_kernel<<<BATCH * 8 * 8 * (NHEAD / 2), 128>>>(qkv, tbl_l, ao);
        gemm_mma<<<dim3(512 / 128, TOK / 128), 256, GEMM_SMEM>>>(
            ao, wo_l, bo_l, x, x, 512, 512, 0);
        ln_kernel<<<TOK, 128>>>(x, ln2_g + l * DD, ln2_b + l * DD, hb);
        gemm_mma<<<dim3(2048 / 128, TOK / 128), 256, GEMM_SMEM>>>(
            hb, w1_l, b1_l, nullptr, hid, 2048, 512, 1);
        gemm_mma<<<dim3(512 / 128, TOK / 128), 256, GEMM_SMEM>>>(
            hid, w2_l, b2_l, x, x, 512, 2048, 0);
    }
}